// round 14
// baseline (speedup 1.0000x reference)
#include <cuda_runtime.h>
#include <cuda_fp16.h>

#define NODES   6272
#define CIN     8
#define COUT    16
#define CAPS    10
#define BATCH   64
#define PAIRS   (BATCH * CAPS)          // 640
#define CHUNK   64
#define NCHUNK  (NODES / CHUNK)         // 98
#define K1_THREADS 256
#define NSLICE  7
#define SLICE   (NODES / NSLICE)        // 896 nodes = 1792 uint4 half-rows
#define P_THREADS 224                   // 7 warps, 8 half-rows per thread
#define P_WARPS 7

// ---------------- device scratch ----------
__device__ __half g_uh[(size_t)PAIRS * NODES * COUT];          // 128.4 MB
__device__ float  g_p0[(size_t)PAIRS * NCHUNK * COUT];
__device__ float  g_ps1[(size_t)PAIRS * NSLICE * (COUT + 1)];
__device__ float  g_ps2[(size_t)PAIRS * NSLICE * (COUT + 1)];
__device__ float  g_v[PAIRS][COUT];     // v0+v1 handoff
__device__ int    g_flag[PAIRS];        // v ready flag   (self-resetting)
__device__ int    g_cons[PAIRS];        // consumer count (self-resetting)
__device__ int    g_ctr1[PAIRS];        // iter-1 fan-in  (self-resetting)
__device__ int    g_ctr2[PAIRS];        // iter-2 fan-in  (self-resetting)

// ---------------- packed f32x2 helpers -------------------------------------
__device__ __forceinline__ unsigned long long pk2(float lo, float hi) {
    unsigned long long r;
    asm("mov.b64 %0, {%1, %2};" : "=l"(r) : "f"(lo), "f"(hi));
    return r;
}
__device__ __forceinline__ void upk2(unsigned long long v, float& lo, float& hi) {
    asm("mov.b64 {%0, %1}, %2;" : "=f"(lo), "=f"(hi) : "l"(v));
}
__device__ __forceinline__ unsigned long long fma2(unsigned long long a,
                                                   unsigned long long b,
                                                   unsigned long long c) {
    unsigned long long d;
    asm("fma.rn.f32x2 %0, %1, %2, %3;" : "=l"(d) : "l"(a), "l"(b), "l"(c));
    return d;
}

// FMA-pipe exp (no MUFU). rel err ~2.4e-6, clamped to +-70.
__device__ __forceinline__ float fexp(float a) {
    a = fminf(fmaxf(a, -70.f), 70.f);
    float zm = fmaf(a, 1.442695041f, 12582912.0f);
    int   n  = __float_as_int(zm);
    float fj = zm - 12582912.0f;
    float f  = fmaf(a, 1.442695041f, -fj);
    float p  = 0.0013333558f;
    p = fmaf(p, f, 0.0096181291f);
    p = fmaf(p, f, 0.055504109f);
    p = fmaf(p, f, 0.24022651f);
    p = fmaf(p, f, 0.69314718f);
    p = fmaf(p, f, 1.0f);
    return p * __int_as_float((n + (127 - 0x4B400000)) << 23);
}

// ---------------------------------------------------------------------------
// K1 (measured-stable R10 state): u_hat -> fp16 + fp32 pass-0 partials.
// ---------------------------------------------------------------------------
__global__ void __launch_bounds__(K1_THREADS, 4)
uhat_kernel(const float* __restrict__ x, const float* __restrict__ W) {
    __shared__ float Ws[CHUNK * CIN * COUT];      // 32 KB
    __shared__ float xs[8 * CHUNK * CIN];         // 16 KB
    __shared__ float psum[8][16][COUT];           // 8 KB

    const int c  = blockIdx.y;
    const int n0 = blockIdx.x * CHUNK;
    const int t    = threadIdx.x;
    const int lane = t & 31;
    const int warp = t >> 5;
    const int n = t >> 2;
    const int q = t & 3;

    const float4* Wg = reinterpret_cast<const float4*>(
        W + ((size_t)c * NODES + n0) * (CIN * COUT));
    float4* Ws4 = reinterpret_cast<float4*>(Ws);
    #pragma unroll
    for (int i = t; i < CHUNK * CIN * COUT / 4; i += K1_THREADS)
        Ws4[i] = Wg[i];
    __syncthreads();

    unsigned long long Wr2[CIN][2];
    #pragma unroll
    for (int i = 0; i < CIN; i++) {
        const float* wp = Ws + n * (CIN * COUT) + i * COUT + q * 4;
        Wr2[i][0] = pk2(wp[0], wp[1]);
        Wr2[i][1] = pk2(wp[2], wp[3]);
    }

    for (int bg = 0; bg < 8; bg++) {
        __syncthreads();
        #pragma unroll
        for (int k = 0; k < 4; k++) {
            int f  = t + k * K1_THREADS;
            int bi = f >> 7, r = f & 127;
            reinterpret_cast<float4*>(xs)[bi * 128 + r] =
                reinterpret_cast<const float4*>(
                    x + ((size_t)(bg * 8 + bi) * NODES + n0) * CIN)[r];
        }
        __syncthreads();

        #pragma unroll 2
        for (int bi = 0; bi < 8; bi++) {
            const int b = bg * 8 + bi;
            const float4* xv4 = reinterpret_cast<const float4*>(
                xs + bi * (CHUNK * CIN) + n * CIN);
            float4 xa = xv4[0];
            float4 xb = xv4[1];
            float xv[CIN] = {xa.x, xa.y, xa.z, xa.w, xb.x, xb.y, xb.z, xb.w};

            unsigned long long o20 = 0ull, o21 = 0ull;
            #pragma unroll
            for (int i = 0; i < CIN; i++) {
                unsigned long long x2 = pk2(xv[i], xv[i]);
                o20 = fma2(x2, Wr2[i][0], o20);
                o21 = fma2(x2, Wr2[i][1], o21);
            }
            float o0, o1, o2, o3;
            upk2(o20, o0, o1);
            upk2(o21, o2, o3);

            __half2 h0 = __floats2half2_rn(o0, o1);
            __half2 h1 = __floats2half2_rn(o2, o3);
            uint2 st = make_uint2(*(unsigned*)&h0, *(unsigned*)&h1);
            *reinterpret_cast<uint2*>(
                g_uh + (((size_t)b * CAPS + c) * NODES + (n0 + n)) * COUT + q * 4) = st;

            float r0 = o0, r1 = o1, r2 = o2, r3 = o3;
            #pragma unroll
            for (int ofs = 4; ofs <= 8; ofs <<= 1) {
                r0 += __shfl_xor_sync(0xffffffffu, r0, ofs);
                r1 += __shfl_xor_sync(0xffffffffu, r1, ofs);
                r2 += __shfl_xor_sync(0xffffffffu, r2, ofs);
                r3 += __shfl_xor_sync(0xffffffffu, r3, ofs);
            }
            if ((lane & 12) == 0) {
                float4* p = reinterpret_cast<float4*>(
                    &psum[bi][warp * 2 + (lane >> 4)][(lane & 3) * 4]);
                *p = make_float4(r0, r1, r2, r3);
            }
        }
        __syncthreads();

        if (t < 128) {
            const int bi = t >> 4, o = t & 15;
            float s = 0.f;
            #pragma unroll
            for (int w = 0; w < 16; w++) s += psum[bi][w][o];
            const int b = bg * 8 + bi;
            g_p0[(((size_t)b * CAPS + c) * NCHUNK + blockIdx.x) * COUT + o] = s;
        }
    }
}

// ---------------------------------------------------------------------------
// Single-read routing: grid (NSLICE, PAIRS), one CTA per (pair, slice) does
// BOTH routing iterations. Slice loaded from DRAM ONCE into registers, stashed
// to a 28 KB SMEM tile during the iter-1 loop; iter-2 re-reads it from SMEM.
// Iter-1 fan-in: last CTA per pair publishes g_v = v0 + v1, release-flag.
// Siblings (dispatch-adjacent -> co-resident) acquire-spin, then iter-2.
// Pairs traversed DESCENDING (catch K1's L2-hot tail). All counters/flags
// self-reset for graph-replay determinism. No deadlock: <=1 pair straddles a
// wave boundary; completed pairs recycle slots so its siblings get scheduled.
// ---------------------------------------------------------------------------
__global__ void __launch_bounds__(P_THREADS, 4)
route_kernel(float* __restrict__ out) {
    __shared__ uint4 tile[SLICE * 2];             // 28672 B slice stash
    __shared__ float vsm[COUT];
    __shared__ float red[P_WARPS][COUT + 1];
    __shared__ int   is_last;

    const int slice = NSLICE - 1 - (int)blockIdx.x;
    const int pair  = PAIRS  - 1 - (int)blockIdx.y;
    const int tid   = threadIdx.x;
    const int lane  = tid & 31;
    const int warp  = tid >> 5;
    const int par   = lane & 1;

    const uint4* __restrict__ base =
        reinterpret_cast<const uint4*>(g_uh) +
        (size_t)pair * (NODES * 2) + slice * (SLICE * 2);

    // front-batch ALL slice loads (8 independent LDG.128 per thread)
    uint4 buf[8];
    #pragma unroll
    for (int k = 0; k < 8; k++) buf[k] = base[k * P_THREADS + tid];

    // ---- prologue (overlaps load latency): v0 from g_p0 ----
    float p0part = 0.f;
    if (lane < COUT) {
        const float* p = g_p0 + (size_t)pair * NCHUNK * COUT + lane;
        #pragma unroll
        for (int k = 0; k < NCHUNK / P_WARPS; k++)          // 14 chunks/warp
            p0part += p[(warp + k * P_WARPS) * COUT];
        red[warp][lane] = p0part;
    }
    __syncthreads();
    if (warp == 0) {
        float s = 0.f;
        if (lane < COUT) {
            #pragma unroll
            for (int w = 0; w < P_WARPS; w++) s += red[w][lane];
            s *= (1.f / (float)NODES);
        }
        float sq = s * s;
        #pragma unroll
        for (int ofs = 16; ofs > 0; ofs >>= 1)
            sq += __shfl_xor_sync(0xffffffffu, sq, ofs);
        float v = s * (sq / ((1.f + sq) * sqrtf(sq)));      // v0
        if (lane < COUT) vsm[lane] = v;
    }
    __syncthreads();

    float vr[8];
    #pragma unroll
    for (int j = 0; j < 8; j++) vr[j] = vsm[par * 8 + j];

    // ---- iter-1 loop: compute from registers, stash to SMEM ----
    float acc[8];
    #pragma unroll
    for (int j = 0; j < 8; j++) acc[j] = 0.f;
    float z = 0.f;

    #pragma unroll
    for (int k = 0; k < 8; k += 2) {
        tile[k * P_THREADS + tid]       = buf[k];
        tile[(k + 1) * P_THREADS + tid] = buf[k + 1];
        float u0[8], u1[8];
        {
            unsigned w0[4] = {buf[k].x, buf[k].y, buf[k].z, buf[k].w};
            unsigned w1[4] = {buf[k+1].x, buf[k+1].y, buf[k+1].z, buf[k+1].w};
            #pragma unroll
            for (int h = 0; h < 4; h++) {
                float2 f0 = __half22float2(*reinterpret_cast<__half2*>(&w0[h]));
                float2 f1 = __half22float2(*reinterpret_cast<__half2*>(&w1[h]));
                u0[2 * h] = f0.x; u0[2 * h + 1] = f0.y;
                u1[2 * h] = f1.x; u1[2 * h + 1] = f1.y;
            }
        }
        float a0 = 0.f, a1 = 0.f;
        #pragma unroll
        for (int j = 0; j < 8; j++) {
            a0 = fmaf(u0[j], vr[j], a0);
            a1 = fmaf(u1[j], vr[j], a1);
        }
        a0 += __shfl_xor_sync(0xffffffffu, a0, 1);
        a1 += __shfl_xor_sync(0xffffffffu, a1, 1);
        float e0 = fexp(a0);
        float e1 = fexp(a1);
        z += e0 + e1;
        #pragma unroll
        for (int j = 0; j < 8; j++) {
            acc[j] = fmaf(e0, u0[j], acc[j]);
            acc[j] = fmaf(e1, u1[j], acc[j]);
        }
    }

    // parity-separated warp reduction
    #pragma unroll
    for (int j = 0; j < 8; j++) {
        float v = acc[j];
        #pragma unroll
        for (int ofs = 16; ofs >= 2; ofs >>= 1)
            v += __shfl_xor_sync(0xffffffffu, v, ofs);
        acc[j] = v;
    }
    #pragma unroll
    for (int ofs = 16; ofs >= 2; ofs >>= 1)
        z += __shfl_xor_sync(0xffffffffu, z, ofs);

    __syncthreads();
    if (lane == 0) {
        #pragma unroll
        for (int j = 0; j < 8; j++) red[warp][j] = acc[j];
        red[warp][COUT] = z;
    } else if (lane == 1) {
        #pragma unroll
        for (int j = 0; j < 8; j++) red[warp][8 + j] = acc[j];
    }
    __syncthreads();
    if (tid < COUT + 1) {
        float s = 0.f;
        #pragma unroll
        for (int w = 0; w < P_WARPS; w++) s += red[w][tid];
        g_ps1[((size_t)pair * NSLICE + slice) * (COUT + 1) + tid] = s;
    }

    // ---- iter-1 fan-in: last CTA publishes v = v0 + v1 ----
    __syncthreads();
    if (tid == 0) {
        __threadfence();
        int old = atomicAdd(&g_ctr1[pair], 1);
        is_last = (old == NSLICE - 1) ? 1 : 0;
        if (is_last) __threadfence();
    }
    __syncthreads();
    if (is_last && warp == 0) {
        float sp = 0.f;
        if (lane < COUT + 1) {
            const float* p = g_ps1 + (size_t)pair * NSLICE * (COUT + 1) + lane;
            #pragma unroll
            for (int sl = 0; sl < NSLICE; sl++) sp += p[sl * (COUT + 1)];
        }
        float zz = __shfl_sync(0xffffffffu, sp, COUT);
        float sj = (lane < COUT) ? sp * (1.f / zz) : 0.f;
        float s2 = sj * sj;
        #pragma unroll
        for (int ofs = 16; ofs > 0; ofs >>= 1)
            s2 += __shfl_xor_sync(0xffffffffu, s2, ofs);
        float kf = s2 / ((1.f + s2) * sqrtf(s2));
        if (lane < COUT)
            g_v[pair][lane] = fmaf(sj, kf, vsm[lane]);      // v0 + v1
        __syncwarp();
        if (lane == 0) {
            g_ctr1[pair] = 0;                 // self-reset
            __threadfence();                  // order g_v before flag
            atomicExch(&g_flag[pair], 1);     // release
        }
    }

    // ---- wait for v, then iter-2 from the SMEM tile ----
    if (tid == 0) {
        int f;
        do {
            asm volatile("ld.global.acquire.gpu.b32 %0, [%1];"
                         : "=r"(f) : "l"(&g_flag[pair]) : "memory");
            if (f) break;
            __nanosleep(32);
        } while (true);
    }
    __syncthreads();
    if (tid < COUT) vsm[tid] = g_v[pair][tid];
    __syncthreads();

    #pragma unroll
    for (int j = 0; j < 8; j++) vr[j] = vsm[par * 8 + j];
    #pragma unroll
    for (int j = 0; j < 8; j++) acc[j] = 0.f;
    z = 0.f;

    #pragma unroll
    for (int k = 0; k < 8; k += 2) {
        uint4 b0 = tile[k * P_THREADS + tid];
        uint4 b1 = tile[(k + 1) * P_THREADS + tid];
        float u0[8], u1[8];
        {
            unsigned w0[4] = {b0.x, b0.y, b0.z, b0.w};
            unsigned w1[4] = {b1.x, b1.y, b1.z, b1.w};
            #pragma unroll
            for (int h = 0; h < 4; h++) {
                float2 f0 = __half22float2(*reinterpret_cast<__half2*>(&w0[h]));
                float2 f1 = __half22float2(*reinterpret_cast<__half2*>(&w1[h]));
                u0[2 * h] = f0.x; u0[2 * h + 1] = f0.y;
                u1[2 * h] = f1.x; u1[2 * h + 1] = f1.y;
            }
        }
        float a0 = 0.f, a1 = 0.f;
        #pragma unroll
        for (int j = 0; j < 8; j++) {
            a0 = fmaf(u0[j], vr[j], a0);
            a1 = fmaf(u1[j], vr[j], a1);
        }
        a0 += __shfl_xor_sync(0xffffffffu, a0, 1);
        a1 += __shfl_xor_sync(0xffffffffu, a1, 1);
        float e0 = fexp(a0);
        float e1 = fexp(a1);
        z += e0 + e1;
        #pragma unroll
        for (int j = 0; j < 8; j++) {
            acc[j] = fmaf(e0, u0[j], acc[j]);
            acc[j] = fmaf(e1, u1[j], acc[j]);
        }
    }

    #pragma unroll
    for (int j = 0; j < 8; j++) {
        float v = acc[j];
        #pragma unroll
        for (int ofs = 16; ofs >= 2; ofs >>= 1)
            v += __shfl_xor_sync(0xffffffffu, v, ofs);
        acc[j] = v;
    }
    #pragma unroll
    for (int ofs = 16; ofs >= 2; ofs >>= 1)
        z += __shfl_xor_sync(0xffffffffu, z, ofs);

    __syncthreads();
    if (lane == 0) {
        #pragma unroll
        for (int j = 0; j < 8; j++) red[warp][j] = acc[j];
        red[warp][COUT] = z;
    } else if (lane == 1) {
        #pragma unroll
        for (int j = 0; j < 8; j++) red[warp][8 + j] = acc[j];
    }
    __syncthreads();
    if (tid < COUT + 1) {
        float s = 0.f;
        #pragma unroll
        for (int w = 0; w < P_WARPS; w++) s += red[w][tid];
        g_ps2[((size_t)pair * NSLICE + slice) * (COUT + 1) + tid] = s;
    }

    // ---- iter-2 fan-in: last CTA writes output ----
    __syncthreads();
    if (tid == 0) {
        __threadfence();
        int old = atomicAdd(&g_ctr2[pair], 1);
        is_last = (old == NSLICE - 1) ? 1 : 0;
        if (is_last) __threadfence();
    }
    __syncthreads();
    if (is_last && warp == 0) {
        float s = 0.f;
        if (lane < COUT + 1) {
            const float* p = g_ps2 + (size_t)pair * NSLICE * (COUT + 1) + lane;
            #pragma unroll
            for (int sl = 0; sl < NSLICE; sl++) s += p[sl * (COUT + 1)];
        }
        float zz = __shfl_sync(0xffffffffu, s, COUT);
        float sj = (lane < COUT) ? s * (1.f / zz) : 0.f;
        float sq = sj * sj;
        #pragma unroll
        for (int ofs = 16; ofs > 0; ofs >>= 1)
            sq += __shfl_xor_sync(0xffffffffu, sq, ofs);
        float kf = sq / ((1.f + sq) * sqrtf(sq));
        if (lane < COUT) out[pair * COUT + lane] = sj * kf;
        if (lane == 0) g_ctr2[pair] = 0;          // self-reset
    }
    // flag reset: 7th consumer (all siblings are past the spin by now)
    if (tid == 0) {
        int o = atomicAdd(&g_cons[pair], 1);
        if (o == NSLICE - 1) {
            g_cons[pair] = 0;
            atomicExch(&g_flag[pair], 0);
        }
    }
}

// ---------------------------------------------------------------------------
extern "C" void kernel_launch(void* const* d_in, const int* in_sizes, int n_in,
                              void* d_out, int out_size) {
    const float* x = (const float*)d_in[0];
    const float* W = (const float*)d_in[1];
    if (in_sizes[0] != BATCH * NODES * CIN) {
        const float* tmp = x; x = W; W = tmp;
    }

    uhat_kernel<<<dim3(NCHUNK, CAPS), K1_THREADS>>>(x, W);
    route_kernel<<<dim3(NSLICE, PAIRS), P_THREADS>>>((float*)d_out);
}

// round 15
// speedup vs baseline: 1.1639x; 1.1639x over previous
#include <cuda_runtime.h>
#include <cuda_fp16.h>

#define NODES   6272
#define CIN     8
#define COUT    16
#define CAPS    10
#define BATCH   64
#define PAIRS   (BATCH * CAPS)          // 640
#define CHUNK   64
#define NCHUNK  (NODES / CHUNK)         // 98
#define K1_THREADS 256
#define NSLICE  7
#define SLICE   (NODES / NSLICE)        // 896 nodes = 1792 uint4 half-rows
#define P_THREADS 224                   // 7 warps
#define P_WARPS 7
#define P_ITERS 4                       // 2 half-rows per thread per iter

// ---------------- device scratch ----------
__device__ __half g_uh[(size_t)PAIRS * NODES * COUT];          // 128.4 MB
__device__ float  g_p0[(size_t)PAIRS * NCHUNK * COUT];
__device__ float  g_ps1[(size_t)PAIRS * NSLICE * (COUT + 1)];
__device__ float  g_ps2[(size_t)PAIRS * NSLICE * (COUT + 1)];
__device__ int    g_ctr[PAIRS];         // fan-in counters (self-resetting)

// ---------------- packed helpers -------------------------------------------
__device__ __forceinline__ unsigned long long pk2(float lo, float hi) {
    unsigned long long r;
    asm("mov.b64 %0, {%1, %2};" : "=l"(r) : "f"(lo), "f"(hi));
    return r;
}
__device__ __forceinline__ void upk2(unsigned long long v, float& lo, float& hi) {
    asm("mov.b64 {%0, %1}, %2;" : "=f"(lo), "=f"(hi) : "l"(v));
}
__device__ __forceinline__ unsigned long long fma2(unsigned long long a,
                                                   unsigned long long b,
                                                   unsigned long long c) {
    unsigned long long d;
    asm("fma.rn.f32x2 %0, %1, %2, %3;" : "=l"(d) : "l"(a), "l"(b), "l"(c));
    return d;
}
__device__ __forceinline__ unsigned hadd2u(unsigned a, unsigned b) {
    __half2 r = __hadd2(*reinterpret_cast<__half2*>(&a),
                        *reinterpret_cast<__half2*>(&b));
    return *reinterpret_cast<unsigned*>(&r);
}

// FMA-pipe exp (no MUFU). rel err ~2.4e-6, clamped to +-70.
__device__ __forceinline__ float fexp(float a) {
    a = fminf(fmaxf(a, -70.f), 70.f);
    float zm = fmaf(a, 1.442695041f, 12582912.0f);
    int   n  = __float_as_int(zm);
    float fj = zm - 12582912.0f;
    float f  = fmaf(a, 1.442695041f, -fj);
    float p  = 0.0013333558f;
    p = fmaf(p, f, 0.0096181291f);
    p = fmaf(p, f, 0.055504109f);
    p = fmaf(p, f, 0.24022651f);
    p = fmaf(p, f, 0.69314718f);
    p = fmaf(p, f, 1.0f);
    return p * __int_as_float((n + (127 - 0x4B400000)) << 23);
}

// ---------------------------------------------------------------------------
// K1: u_hat -> fp16 + pass-0 partials. SHFL diet: node-pair reduce in fp16x2
// (2 SHFL + 1 HADD2 per value-pair instead of 8 fp32 SHFLs), pairs stored to
// psum[bi][32][4] (uint2); per-bg tail reduces 32 slots in fp32.
// Smem: W region (32 KB) is DEAD after the reg load -> unioned with xs+psum.
// ---------------------------------------------------------------------------
__global__ void __launch_bounds__(K1_THREADS, 4)
uhat_kernel(const float* __restrict__ x, const float* __restrict__ W) {
    __shared__ __align__(16) char smbuf[32768];   // union: Ws | xs+psum
    float* Ws = reinterpret_cast<float*>(smbuf);                 // [8192]
    float* xs = reinterpret_cast<float*>(smbuf);                 // [4096]
    uint2 (*psum)[32][4] =
        reinterpret_cast<uint2(*)[32][4]>(smbuf + 16384);        // [8][32][4]

    const int c  = blockIdx.y;
    const int n0 = blockIdx.x * CHUNK;
    const int t    = threadIdx.x;
    const int lane = t & 31;
    const int warp = t >> 5;
    const int n = t >> 2;
    const int q = t & 3;

    // stage W chunk, pull into registers, then the region is reused
    const float4* Wg = reinterpret_cast<const float4*>(
        W + ((size_t)c * NODES + n0) * (CIN * COUT));
    float4* Ws4 = reinterpret_cast<float4*>(Ws);
    #pragma unroll
    for (int i = t; i < CHUNK * CIN * COUT / 4; i += K1_THREADS)
        Ws4[i] = Wg[i];
    __syncthreads();

    unsigned long long Wr2[CIN][2];
    #pragma unroll
    for (int i = 0; i < CIN; i++) {
        const float* wp = Ws + n * (CIN * COUT) + i * COUT + q * 4;
        Wr2[i][0] = pk2(wp[0], wp[1]);
        Wr2[i][1] = pk2(wp[2], wp[3]);
    }

    for (int bg = 0; bg < 8; bg++) {
        __syncthreads();   // protects Ws->xs reuse and psum tail reads
        #pragma unroll
        for (int k = 0; k < 4; k++) {
            int f  = t + k * K1_THREADS;
            int bi = f >> 7, r = f & 127;
            reinterpret_cast<float4*>(xs)[bi * 128 + r] =
                reinterpret_cast<const float4*>(
                    x + ((size_t)(bg * 8 + bi) * NODES + n0) * CIN)[r];
        }
        __syncthreads();

        #pragma unroll 2
        for (int bi = 0; bi < 8; bi++) {
            const int b = bg * 8 + bi;
            const float4* xv4 = reinterpret_cast<const float4*>(
                xs + bi * (CHUNK * CIN) + n * CIN);
            float4 xa = xv4[0];
            float4 xb = xv4[1];
            float xv[CIN] = {xa.x, xa.y, xa.z, xa.w, xb.x, xb.y, xb.z, xb.w};

            unsigned long long o20 = 0ull, o21 = 0ull;
            #pragma unroll
            for (int i = 0; i < CIN; i++) {
                unsigned long long x2 = pk2(xv[i], xv[i]);
                o20 = fma2(x2, Wr2[i][0], o20);
                o21 = fma2(x2, Wr2[i][1], o21);
            }
            float o0, o1, o2, o3;
            upk2(o20, o0, o1);
            upk2(o21, o2, o3);

            __half2 h0 = __floats2half2_rn(o0, o1);
            __half2 h1 = __floats2half2_rn(o2, o3);
            unsigned u0 = *reinterpret_cast<unsigned*>(&h0);
            unsigned u1 = *reinterpret_cast<unsigned*>(&h1);
            *reinterpret_cast<uint2*>(
                g_uh + (((size_t)b * CAPS + c) * NODES + (n0 + n)) * COUT + q * 4)
                = make_uint2(u0, u1);

            // fp16x2 node-pair reduce (node bit0 = lane bit2): 2 SHFL + HADD2
            unsigned s0 = hadd2u(u0, __shfl_xor_sync(0xffffffffu, u0, 4));
            unsigned s1 = hadd2u(u1, __shfl_xor_sync(0xffffffffu, u1, 4));
            if ((lane & 4) == 0) {   // lanes 0-3, 8-11, 16-19, 24-27
                psum[bi][warp * 4 + (lane >> 3)][lane & 3] = make_uint2(s0, s1);
            }
            // NO barrier — each warp owns its psum slots.
        }
        __syncthreads();

        if (t < 128) {
            const int bi = t >> 4, o = t & 15;
            const int qq = o >> 2, j = o & 3;
            float s = 0.f;
            #pragma unroll
            for (int w = 0; w < 32; w++) {
                uint2 v = psum[bi][w][qq];
                unsigned h = (j < 2) ? v.x : v.y;
                float2 f = __half22float2(*reinterpret_cast<__half2*>(&h));
                s += (j & 1) ? f.y : f.x;
            }
            const int b = bg * 8 + bi;
            g_p0[(((size_t)b * CAPS + c) * NCHUNK + blockIdx.x) * COUT + o] = s;
        }
    }
}

// ---------------------------------------------------------------------------
// Pass kernel (exact R10-measured body): half-row lane-paired, 2 rows/thread/
// iter, depth-1 prefetch. L2-residency choreography: mode 0 DESCENDING,
// mode 1 ASCENDING. Prologue computes v0 from g_p0 in-CTA; mode 1 folds
// squash(reduce g_ps1) so v = v0 + v1, and the LAST CTA per pair does final
// reduce+squash+output (counter self-resets for graph replay).
// ---------------------------------------------------------------------------
__global__ void __launch_bounds__(P_THREADS, 5)
pass_kernel(int mode, float* __restrict__ out) {
    __shared__ float vsm[COUT];
    __shared__ float red[P_WARPS][COUT + 1];
    __shared__ int   is_last;

    const int slice = (mode == 0) ? (NSLICE - 1 - (int)blockIdx.x) : (int)blockIdx.x;
    const int pair  = (mode == 0) ? (PAIRS  - 1 - (int)blockIdx.y) : (int)blockIdx.y;
    const int tid   = threadIdx.x;
    const int lane  = tid & 31;
    const int warp  = tid >> 5;
    const int par   = lane & 1;

    const uint4* __restrict__ base =
        reinterpret_cast<const uint4*>(g_uh) +
        (size_t)pair * (NODES * 2) + slice * (SLICE * 2);

    uint4 cur0 = base[tid];
    uint4 cur1 = base[tid + P_THREADS];

    float p0part = 0.f;
    if (lane < COUT) {
        const float* p = g_p0 + (size_t)pair * NCHUNK * COUT + lane;
        #pragma unroll
        for (int k = 0; k < NCHUNK / P_WARPS; k++)
            p0part += p[(warp + k * P_WARPS) * COUT];
        red[warp][lane] = p0part;
    }
    __syncthreads();

    if (warp == 0) {
        float s = 0.f;
        if (lane < COUT) {
            #pragma unroll
            for (int w = 0; w < P_WARPS; w++) s += red[w][lane];
            s *= (1.f / (float)NODES);
        }
        float sq = s * s;
        #pragma unroll
        for (int ofs = 16; ofs > 0; ofs >>= 1)
            sq += __shfl_xor_sync(0xffffffffu, sq, ofs);
        float v = s * (sq / ((1.f + sq) * sqrtf(sq)));      // v0

        if (mode == 1) {
            float sp = 0.f;
            if (lane < COUT + 1) {
                const float* p = g_ps1 + (size_t)pair * NSLICE * (COUT + 1) + lane;
                #pragma unroll
                for (int sl = 0; sl < NSLICE; sl++) sp += p[sl * (COUT + 1)];
            }
            float zz = __shfl_sync(0xffffffffu, sp, COUT);
            float sj = (lane < COUT) ? sp * (1.f / zz) : 0.f;
            float s2 = sj * sj;
            #pragma unroll
            for (int ofs = 16; ofs > 0; ofs >>= 1)
                s2 += __shfl_xor_sync(0xffffffffu, s2, ofs);
            v = fmaf(sj, s2 / ((1.f + s2) * sqrtf(s2)), v); // + v1
        }
        if (lane < COUT) vsm[lane] = v;
    }
    __syncthreads();

    float vr[8];
    #pragma unroll
    for (int j = 0; j < 8; j++) vr[j] = vsm[par * 8 + j];

    float acc[8];
    #pragma unroll
    for (int j = 0; j < 8; j++) acc[j] = 0.f;
    float z = 0.f;

    #pragma unroll
    for (int k = 0; k < P_ITERS; k++) {
        uint4 n0, n1;
        if (k < P_ITERS - 1) {
            n0 = base[(k + 1) * (2 * P_THREADS) + tid];
            n1 = base[(k + 1) * (2 * P_THREADS) + P_THREADS + tid];
        }

        float u0[8], u1[8];
        {
            unsigned w0[4] = {cur0.x, cur0.y, cur0.z, cur0.w};
            unsigned w1[4] = {cur1.x, cur1.y, cur1.z, cur1.w};
            #pragma unroll
            for (int h = 0; h < 4; h++) {
                float2 f0 = __half22float2(*reinterpret_cast<__half2*>(&w0[h]));
                float2 f1 = __half22float2(*reinterpret_cast<__half2*>(&w1[h]));
                u0[2 * h] = f0.x; u0[2 * h + 1] = f0.y;
                u1[2 * h] = f1.x; u1[2 * h + 1] = f1.y;
            }
        }
        float a0 = 0.f, a1 = 0.f;
        #pragma unroll
        for (int j = 0; j < 8; j++) {
            a0 = fmaf(u0[j], vr[j], a0);
            a1 = fmaf(u1[j], vr[j], a1);
        }
        a0 += __shfl_xor_sync(0xffffffffu, a0, 1);
        a1 += __shfl_xor_sync(0xffffffffu, a1, 1);
        float e0 = fexp(a0);
        float e1 = fexp(a1);
        z += e0 + e1;
        #pragma unroll
        for (int j = 0; j < 8; j++) {
            acc[j] = fmaf(e0, u0[j], acc[j]);
            acc[j] = fmaf(e1, u1[j], acc[j]);
        }
        cur0 = n0;
        cur1 = n1;
    }

    #pragma unroll
    for (int j = 0; j < 8; j++) {
        float v = acc[j];
        #pragma unroll
        for (int ofs = 16; ofs >= 2; ofs >>= 1)
            v += __shfl_xor_sync(0xffffffffu, v, ofs);
        acc[j] = v;
    }
    #pragma unroll
    for (int ofs = 16; ofs >= 2; ofs >>= 1)
        z += __shfl_xor_sync(0xffffffffu, z, ofs);

    __syncthreads();
    if (lane == 0) {
        #pragma unroll
        for (int j = 0; j < 8; j++) red[warp][j] = acc[j];
        red[warp][COUT] = z;
    } else if (lane == 1) {
        #pragma unroll
        for (int j = 0; j < 8; j++) red[warp][8 + j] = acc[j];
    }
    __syncthreads();

    if (tid < COUT + 1) {
        float s = 0.f;
        #pragma unroll
        for (int w = 0; w < P_WARPS; w++) s += red[w][tid];
        float* dst = (mode == 0) ? g_ps1 : g_ps2;
        dst[((size_t)pair * NSLICE + slice) * (COUT + 1) + tid] = s;
    }

    if (mode == 1) {
        __syncthreads();
        if (tid == 0) {
            __threadfence();
            int old = atomicAdd(&g_ctr[pair], 1);
            is_last = (old == NSLICE - 1) ? 1 : 0;
            if (is_last) __threadfence();
        }
        __syncthreads();
        if (is_last && warp == 0) {
            float s = 0.f;
            if (lane < COUT + 1) {
                const float* p =
                    g_ps2 + (size_t)pair * NSLICE * (COUT + 1) + lane;
                #pragma unroll
                for (int sl = 0; sl < NSLICE; sl++) s += p[sl * (COUT + 1)];
            }
            float zz = __shfl_sync(0xffffffffu, s, COUT);
            float sj = (lane < COUT) ? s * (1.f / zz) : 0.f;
            float sq = sj * sj;
            #pragma unroll
            for (int ofs = 16; ofs > 0; ofs >>= 1)
                sq += __shfl_xor_sync(0xffffffffu, sq, ofs);
            float kf = sq / ((1.f + sq) * sqrtf(sq));
            if (lane < COUT) out[pair * COUT + lane] = sj * kf;
            if (lane == 0) g_ctr[pair] = 0;   // self-reset for next replay
        }
    }
}

// ---------------------------------------------------------------------------
extern "C" void kernel_launch(void* const* d_in, const int* in_sizes, int n_in,
                              void* d_out, int out_size) {
    const float* x = (const float*)d_in[0];
    const float* W = (const float*)d_in[1];
    if (in_sizes[0] != BATCH * NODES * CIN) {
        const float* tmp = x; x = W; W = tmp;
    }

    uhat_kernel<<<dim3(NCHUNK, CAPS), K1_THREADS>>>(x, W);
    pass_kernel<<<dim3(NSLICE, PAIRS), P_THREADS>>>(0, nullptr);
    pass_kernel<<<dim3(NSLICE, PAIRS), P_THREADS>>>(1, (float*)d_out);
}